// round 12
// baseline (speedup 1.0000x reference)
#include <cuda_runtime.h>
#include <cuda_fp16.h>
#include <cstdint>

#define F_DIM     48
#define CHUNKS    12             // 48 floats = 12 float4 per node (f32 side)
#define XH_STRIDE 64             // fp16 row padded to 64 halves = 128B
#define N_NODES   100000
#define N_EDGES   1600000
#define EDGES_PER_WARP 32

#define SCAN_TPB   1024
#define SCAN_ELEMS (N_NODES + 1)
#define SCAN_NBLK  ((SCAN_ELEMS + SCAN_TPB - 1) / SCAN_TPB)     // 98

// ---------------------------------------------------------------------------
// Scratch (__device__ globals — no allocation)
// ---------------------------------------------------------------------------
__device__ int    g_count[N_NODES + 1];      // counts -> block-local scan -> cursors
__device__ int    g_blocksums[128];
__device__ int4   g_emeta[N_EDGES];          // row-sorted {col, row, val-bits, 0}
__device__ __half g_xh[N_NODES * XH_STRIDE]; // fp16 x*w, 128B rows (12.8MB)

// ---------------------------------------------------------------------------
// 1. fused: xh = x*w -> fp16 (padded rows), zero out, histogram RED.
// ---------------------------------------------------------------------------
__global__ __launch_bounds__(256)
void convert_hist_kernel(const float4* __restrict__ x4,
                         const float4* __restrict__ w4,
                         const int*    __restrict__ rows,
                         float4*       __restrict__ out4,
                         int n4, int nE) {
    int i = blockIdx.x * blockDim.x + threadIdx.x;
    if (i < n4) {
        int node = i / CHUNKS;
        int c    = i - node * CHUNKS;
        float4 v  = x4[i];
        float4 wv = __ldg(w4 + c);
        v.x *= wv.x; v.y *= wv.y; v.z *= wv.z; v.w *= wv.w;
        __half2 h0 = __floats2half2_rn(v.x, v.y);
        __half2 h1 = __floats2half2_rn(v.z, v.w);
        uint2 packed;
        packed.x = *reinterpret_cast<unsigned int*>(&h0);
        packed.y = *reinterpret_cast<unsigned int*>(&h1);
        *reinterpret_cast<uint2*>(g_xh + (size_t)node * XH_STRIDE + c * 4) = packed;
        out4[i] = make_float4(0.f, 0.f, 0.f, 0.f);   // RED target must be 0
    }
    int e = i * 4;
    if (e + 3 < nE) {
        int4 r = *reinterpret_cast<const int4*>(rows + e);
        atomicAdd(&g_count[r.x + 1], 1);
        atomicAdd(&g_count[r.y + 1], 1);
        atomicAdd(&g_count[r.z + 1], 1);
        atomicAdd(&g_count[r.w + 1], 1);
    } else if (e < nE) {
        for (; e < nE; e++) atomicAdd(&g_count[rows[e] + 1], 1);
    }
}

// ---------------------------------------------------------------------------
// 2. scan1: block-local inclusive scan + block sums (consumer-side fixup)
// ---------------------------------------------------------------------------
__global__ __launch_bounds__(SCAN_TPB)
void scan1_kernel() {
    __shared__ int buf[2][SCAN_TPB];
    int t = threadIdx.x;
    int idx = blockIdx.x * SCAN_TPB + t;
    int v = (idx < SCAN_ELEMS) ? g_count[idx] : 0;
    int src = 0;
    buf[0][t] = v;
    __syncthreads();
    #pragma unroll
    for (int off = 1; off < SCAN_TPB; off <<= 1) {
        int val = buf[src][t];
        if (t >= off) val += buf[src][t - off];
        buf[src ^ 1][t] = val;
        src ^= 1;
        __syncthreads();
    }
    if (idx < SCAN_ELEMS) g_count[idx] = buf[src][t];
    if (t == SCAN_TPB - 1) g_blocksums[blockIdx.x] = buf[src][t];
}

// ---------------------------------------------------------------------------
// Helper: exclusive prefixes of the <=98 block sums, in smem.
// ---------------------------------------------------------------------------
__device__ __forceinline__ void load_block_prefixes(int* s_bpre, int t) {
    __shared__ int tmp[2][128];
    if (t < 128) tmp[0][t] = (t < SCAN_NBLK) ? g_blocksums[t] : 0;
    __syncthreads();
    int src = 0;
    #pragma unroll
    for (int off = 1; off < 128; off <<= 1) {
        if (t < 128) {
            int val = tmp[src][t];
            if (t >= off) val += tmp[src][t - off];
            tmp[src ^ 1][t] = val;
        }
        src ^= 1;
        __syncthreads();
    }
    if (t < 128) s_bpre[t] = (t == 0) ? 0 : tmp[src][t - 1];
    __syncthreads();
}

// ---------------------------------------------------------------------------
// 3. reorder: p = atomicAdd(&g_count[row],1) + bprefix[row>>10].
//    4 edges/thread. Writes {col,row,val,0} (16B) so segsum never needs CSR.
// ---------------------------------------------------------------------------
__global__ __launch_bounds__(256)
void reorder_kernel(const int*   __restrict__ rows,
                    const int*   __restrict__ cols,
                    const float* __restrict__ vals, int nE) {
    __shared__ int s_bpre[128];
    load_block_prefixes(s_bpre, threadIdx.x);

    int q = blockIdx.x * blockDim.x + threadIdx.x;
    int e = q * 4;
    if (e + 3 < nE) {
        int4   r  = *reinterpret_cast<const int4*>(rows + e);
        int4   cc = *reinterpret_cast<const int4*>(cols + e);
        float4 vv = *reinterpret_cast<const float4*>(vals + e);
        int p0 = atomicAdd(&g_count[r.x], 1) + s_bpre[r.x >> 10];
        int p1 = atomicAdd(&g_count[r.y], 1) + s_bpre[r.y >> 10];
        int p2 = atomicAdd(&g_count[r.z], 1) + s_bpre[r.z >> 10];
        int p3 = atomicAdd(&g_count[r.w], 1) + s_bpre[r.w >> 10];
        g_emeta[p0] = make_int4(cc.x, r.x, __float_as_int(vv.x), 0);
        g_emeta[p1] = make_int4(cc.y, r.y, __float_as_int(vv.y), 0);
        g_emeta[p2] = make_int4(cc.z, r.z, __float_as_int(vv.z), 0);
        g_emeta[p3] = make_int4(cc.w, r.w, __float_as_int(vv.w), 0);
    } else if (e < nE) {
        for (; e < nE; e++) {
            int r = rows[e];
            int p = atomicAdd(&g_count[r], 1) + s_bpre[r >> 10];
            g_emeta[p] = make_int4(cols[e], r, __float_as_int(vals[e]), 0);
        }
    }
}

// ---------------------------------------------------------------------------
// 4. segsum: each warp owns EXACTLY 32 consecutive row-sorted edges.
//    One edge per warp-step; lane l owns features [2l, 2l+2).
//    Warp-uniform row-change branch; flush via red.v2 (lanes 0..23).
// ---------------------------------------------------------------------------
__device__ __forceinline__ void flush_row(float* __restrict__ out,
                                          int row, int lane, float2 acc) {
    if (lane < 24) {
        float* dst = out + (size_t)row * F_DIM + lane * 2;
        asm volatile("red.global.add.v2.f32 [%0], {%1, %2};"
                     :: "l"(dst), "f"(acc.x), "f"(acc.y) : "memory");
    }
}

__global__ __launch_bounds__(256)
void segsum_kernel(float* __restrict__ out, int nE) {
    int gwarp = (blockIdx.x * blockDim.x + threadIdx.x) >> 5;
    int lane  = threadIdx.x & 31;
    int e0 = gwarp * EDGES_PER_WARP;
    if (e0 >= nE) return;
    int n = nE - e0;
    if (n > EDGES_PER_WARP) n = EDGES_PER_WARP;

    int    cur_row = -1;
    float2 acc = make_float2(0.f, 0.f);

    int k = 0;
    for (; k + 3 < n; k += 4) {
        // 4 independent meta loads (broadcast, 1 line each)
        int4 m0 = __ldg(g_emeta + e0 + k + 0);
        int4 m1 = __ldg(g_emeta + e0 + k + 1);
        int4 m2 = __ldg(g_emeta + e0 + k + 2);
        int4 m3 = __ldg(g_emeta + e0 + k + 3);
        // 4 independent gathers (each exactly 1 line across the warp)
        unsigned h0 = *reinterpret_cast<const unsigned*>(g_xh + (size_t)m0.x * XH_STRIDE + lane * 2);
        unsigned h1 = *reinterpret_cast<const unsigned*>(g_xh + (size_t)m1.x * XH_STRIDE + lane * 2);
        unsigned h2 = *reinterpret_cast<const unsigned*>(g_xh + (size_t)m2.x * XH_STRIDE + lane * 2);
        unsigned h3 = *reinterpret_cast<const unsigned*>(g_xh + (size_t)m3.x * XH_STRIDE + lane * 2);

        #pragma unroll
        for (int j = 0; j < 4; j++) {
            int4 m = (j == 0) ? m0 : (j == 1) ? m1 : (j == 2) ? m2 : m3;
            unsigned hb = (j == 0) ? h0 : (j == 1) ? h1 : (j == 2) ? h2 : h3;
            if (m.y != cur_row) {                 // warp-uniform
                if (cur_row >= 0) flush_row(out, cur_row, lane, acc);
                acc = make_float2(0.f, 0.f);
                cur_row = m.y;
            }
            __half2 hh = *reinterpret_cast<__half2*>(&hb);
            float2 xv = __half22float2(hh);
            float  v  = __int_as_float(m.z);
            acc.x += v * xv.x;
            acc.y += v * xv.y;
        }
    }
    for (; k < n; k++) {                          // tail (rare)
        int4 m = __ldg(g_emeta + e0 + k);
        unsigned hb = *reinterpret_cast<const unsigned*>(g_xh + (size_t)m.x * XH_STRIDE + lane * 2);
        if (m.y != cur_row) {
            if (cur_row >= 0) flush_row(out, cur_row, lane, acc);
            acc = make_float2(0.f, 0.f);
            cur_row = m.y;
        }
        __half2 hh = *reinterpret_cast<__half2*>(&hb);
        float2 xv = __half22float2(hh);
        float  v  = __int_as_float(m.z);
        acc.x += v * xv.x;
        acc.y += v * xv.y;
    }
    if (cur_row >= 0) flush_row(out, cur_row, lane, acc);
}

// ---------------------------------------------------------------------------
// Launch: memset -> fused(convert+zero+hist) -> scan1 -> reorder -> segsum
// Inputs: 0 x[1,100000,48] f32 | 1 w[1,48] f32 | 2 rows[1.6M] i32
//         3 cols[1.6M] i32     | 4 vals[1.6M] f32
// Output: f32 [100000, 48]
// ---------------------------------------------------------------------------
extern "C" void kernel_launch(void* const* d_in, const int* in_sizes, int n_in,
                              void* d_out, int out_size) {
    const float* x    = (const float*)d_in[0];
    const float* w    = (const float*)d_in[1];
    const int*   rows = (const int*)  d_in[2];
    const int*   cols = (const int*)  d_in[3];
    const float* vals = (const float*)d_in[4];
    float*       out  = (float*)d_out;

    const int nE = in_sizes[2];
    const int n4 = N_NODES * CHUNKS;               // 1.2M float4 groups

    // 0. zero histogram
    void* count_ptr = nullptr;
    cudaGetSymbolAddress(&count_ptr, g_count);
    cudaMemsetAsync(count_ptr, 0, (N_NODES + 1) * sizeof(int), 0);

    // 1. fused convert (x*w -> fp16) + zero out + histogram
    convert_hist_kernel<<<(n4 + 255) / 256, 256>>>((const float4*)x,
                                                   (const float4*)w,
                                                   rows, (float4*)out,
                                                   n4, nE);
    // 2. block-local scan
    scan1_kernel<<<SCAN_NBLK, SCAN_TPB>>>();
    // 3. reorder
    {
        int nq = (nE + 3) / 4;
        reorder_kernel<<<(nq + 255) / 256, 256>>>(rows, cols, vals, nE);
    }
    // 4. balanced segmented sum (1 warp per 32 edges)
    {
        int nWarps = (nE + EDGES_PER_WARP - 1) / EDGES_PER_WARP;  // 50000
        int threads = 256;
        int blocks = (nWarps * 32 + threads - 1) / threads;
        segsum_kernel<<<blocks, threads>>>(out, nE);
    }
}

// round 13
// speedup vs baseline: 1.1775x; 1.1775x over previous
#include <cuda_runtime.h>
#include <cuda_fp16.h>
#include <cstdint>

#define F_DIM     48
#define CHUNKS    12             // 48 floats = 12 float4 per node
#define XH_STRIDE 64             // fp16 row padded to 64 halves = 128B
#define N_NODES   100000
#define N_EDGES   1600000
#define WIN       16             // edges per 12-lane group (fixed window)
#define GRP_TPB   384            // 32 groups of 12 lanes per block

#define SCAN_TPB   1024
#define SCAN_ELEMS (N_NODES + 1)
#define SCAN_NBLK  ((SCAN_ELEMS + SCAN_TPB - 1) / SCAN_TPB)     // 98

// ---------------------------------------------------------------------------
// Scratch (__device__ globals — no allocation)
// ---------------------------------------------------------------------------
__device__ int    g_count[N_NODES + 1];      // counts -> block-local scan -> cursors
__device__ int    g_blocksums[128];
__device__ int4   g_emeta[N_EDGES];          // row-sorted {col, row, val-bits, 0}
__device__ __half g_xh[N_NODES * XH_STRIDE]; // fp16 x*w, 128B rows (12.8MB)

// ---------------------------------------------------------------------------
// 1. fused: xh = x*w -> fp16 (padded rows), zero out, histogram RED.
// ---------------------------------------------------------------------------
__global__ __launch_bounds__(256)
void convert_hist_kernel(const float4* __restrict__ x4,
                         const float4* __restrict__ w4,
                         const int*    __restrict__ rows,
                         float4*       __restrict__ out4,
                         int n4, int nE) {
    int i = blockIdx.x * blockDim.x + threadIdx.x;
    if (i < n4) {
        int node = i / CHUNKS;
        int c    = i - node * CHUNKS;
        float4 v  = x4[i];
        float4 wv = __ldg(w4 + c);
        v.x *= wv.x; v.y *= wv.y; v.z *= wv.z; v.w *= wv.w;
        __half2 h0 = __floats2half2_rn(v.x, v.y);
        __half2 h1 = __floats2half2_rn(v.z, v.w);
        uint2 packed;
        packed.x = *reinterpret_cast<unsigned int*>(&h0);
        packed.y = *reinterpret_cast<unsigned int*>(&h1);
        *reinterpret_cast<uint2*>(g_xh + (size_t)node * XH_STRIDE + c * 4) = packed;
        out4[i] = make_float4(0.f, 0.f, 0.f, 0.f);   // RED target must be 0
    }
    int e = i * 4;
    if (e + 3 < nE) {
        int4 r = *reinterpret_cast<const int4*>(rows + e);
        atomicAdd(&g_count[r.x + 1], 1);
        atomicAdd(&g_count[r.y + 1], 1);
        atomicAdd(&g_count[r.z + 1], 1);
        atomicAdd(&g_count[r.w + 1], 1);
    } else if (e < nE) {
        for (; e < nE; e++) atomicAdd(&g_count[rows[e] + 1], 1);
    }
}

// ---------------------------------------------------------------------------
// 2. scan1: block-local inclusive scan + block sums (consumer-side fixup)
// ---------------------------------------------------------------------------
__global__ __launch_bounds__(SCAN_TPB)
void scan1_kernel() {
    __shared__ int buf[2][SCAN_TPB];
    int t = threadIdx.x;
    int idx = blockIdx.x * SCAN_TPB + t;
    int v = (idx < SCAN_ELEMS) ? g_count[idx] : 0;
    int src = 0;
    buf[0][t] = v;
    __syncthreads();
    #pragma unroll
    for (int off = 1; off < SCAN_TPB; off <<= 1) {
        int val = buf[src][t];
        if (t >= off) val += buf[src][t - off];
        buf[src ^ 1][t] = val;
        src ^= 1;
        __syncthreads();
    }
    if (idx < SCAN_ELEMS) g_count[idx] = buf[src][t];
    if (t == SCAN_TPB - 1) g_blocksums[blockIdx.x] = buf[src][t];
}

// ---------------------------------------------------------------------------
// Helper: exclusive prefixes of the <=98 block sums, in smem.
// ---------------------------------------------------------------------------
__device__ __forceinline__ void load_block_prefixes(int* s_bpre, int t) {
    __shared__ int tmp[2][128];
    if (t < 128) tmp[0][t] = (t < SCAN_NBLK) ? g_blocksums[t] : 0;
    __syncthreads();
    int src = 0;
    #pragma unroll
    for (int off = 1; off < 128; off <<= 1) {
        if (t < 128) {
            int val = tmp[src][t];
            if (t >= off) val += tmp[src][t - off];
            tmp[src ^ 1][t] = val;
        }
        src ^= 1;
        __syncthreads();
    }
    if (t < 128) s_bpre[t] = (t == 0) ? 0 : tmp[src][t - 1];
    __syncthreads();
}

// ---------------------------------------------------------------------------
// 3. reorder: p = atomicAdd(&g_count[row],1) + bprefix[row>>10].
//    4 edges/thread. Writes {col,row,val,0} so the gather needs no CSR reads.
// ---------------------------------------------------------------------------
__global__ __launch_bounds__(256)
void reorder_kernel(const int*   __restrict__ rows,
                    const int*   __restrict__ cols,
                    const float* __restrict__ vals, int nE) {
    __shared__ int s_bpre[128];
    load_block_prefixes(s_bpre, threadIdx.x);

    int q = blockIdx.x * blockDim.x + threadIdx.x;
    int e = q * 4;
    if (e + 3 < nE) {
        int4   r  = *reinterpret_cast<const int4*>(rows + e);
        int4   cc = *reinterpret_cast<const int4*>(cols + e);
        float4 vv = *reinterpret_cast<const float4*>(vals + e);
        int p0 = atomicAdd(&g_count[r.x], 1) + s_bpre[r.x >> 10];
        int p1 = atomicAdd(&g_count[r.y], 1) + s_bpre[r.y >> 10];
        int p2 = atomicAdd(&g_count[r.z], 1) + s_bpre[r.z >> 10];
        int p3 = atomicAdd(&g_count[r.w], 1) + s_bpre[r.w >> 10];
        g_emeta[p0] = make_int4(cc.x, r.x, __float_as_int(vv.x), 0);
        g_emeta[p1] = make_int4(cc.y, r.y, __float_as_int(vv.y), 0);
        g_emeta[p2] = make_int4(cc.z, r.z, __float_as_int(vv.z), 0);
        g_emeta[p3] = make_int4(cc.w, r.w, __float_as_int(vv.w), 0);
    } else if (e < nE) {
        for (; e < nE; e++) {
            int r = rows[e];
            int p = atomicAdd(&g_count[r], 1) + s_bpre[r >> 10];
            g_emeta[p] = make_int4(cols[e], r, __float_as_int(vals[e]), 0);
        }
    }
}

// ---------------------------------------------------------------------------
// 4. windowed gather: each 12-lane group owns EXACTLY 16 consecutive
//    row-sorted edges (perfect balance). Lane c owns features [4c,4c+4).
//    Row boundary -> predicated red.v4 flush (~2 per window).
//    4-deep meta+gather prefetch; branches gate only accumulation.
// ---------------------------------------------------------------------------
__device__ __forceinline__ float4 cvt_h8(uint2 raw) {
    __half2 h0 = *reinterpret_cast<__half2*>(&raw.x);
    __half2 h1 = *reinterpret_cast<__half2*>(&raw.y);
    float2 f0 = __half22float2(h0);
    float2 f1 = __half22float2(h1);
    return make_float4(f0.x, f0.y, f1.x, f1.y);
}

__device__ __forceinline__ void flush4(float* __restrict__ out,
                                       int row, int c, float4 acc) {
    float* dst = out + (size_t)row * F_DIM + c * 4;
    asm volatile("red.global.add.v4.f32 [%0], {%1, %2, %3, %4};"
                 :: "l"(dst), "f"(acc.x), "f"(acc.y), "f"(acc.z), "f"(acc.w)
                 : "memory");
}

__global__ __launch_bounds__(GRP_TPB)
void gatherw_kernel(float* __restrict__ out, int nE) {
    int t   = threadIdx.x;
    int grp = t / 12;               // 0..31 within block
    int c   = t - grp * 12;         // 0..11 feature chunk
    int e0  = (blockIdx.x * 32 + grp) * WIN;
    if (e0 >= nE) return;
    int eend = e0 + WIN < nE ? e0 + WIN : nE;

    int    cur = -1;
    float4 acc = make_float4(0.f, 0.f, 0.f, 0.f);

    int e = e0;
    for (; e + 3 < eend; e += 4) {
        int4 m0 = __ldg(g_emeta + e + 0);
        int4 m1 = __ldg(g_emeta + e + 1);
        int4 m2 = __ldg(g_emeta + e + 2);
        int4 m3 = __ldg(g_emeta + e + 3);
        uint2 h0 = *reinterpret_cast<const uint2*>(g_xh + (size_t)m0.x * XH_STRIDE + c * 4);
        uint2 h1 = *reinterpret_cast<const uint2*>(g_xh + (size_t)m1.x * XH_STRIDE + c * 4);
        uint2 h2 = *reinterpret_cast<const uint2*>(g_xh + (size_t)m2.x * XH_STRIDE + c * 4);
        uint2 h3 = *reinterpret_cast<const uint2*>(g_xh + (size_t)m3.x * XH_STRIDE + c * 4);

        #pragma unroll
        for (int j = 0; j < 4; j++) {
            int4  m = (j == 0) ? m0 : (j == 1) ? m1 : (j == 2) ? m2 : m3;
            uint2 h = (j == 0) ? h0 : (j == 1) ? h1 : (j == 2) ? h2 : h3;
            if (m.y != cur) {
                if (cur >= 0) flush4(out, cur, c, acc);
                acc = make_float4(0.f, 0.f, 0.f, 0.f);
                cur = m.y;
            }
            float4 a = cvt_h8(h);
            float  v = __int_as_float(m.z);
            acc.x += v * a.x;
            acc.y += v * a.y;
            acc.z += v * a.z;
            acc.w += v * a.w;
        }
    }
    for (; e < eend; e++) {
        int4  m = __ldg(g_emeta + e);
        uint2 h = *reinterpret_cast<const uint2*>(g_xh + (size_t)m.x * XH_STRIDE + c * 4);
        if (m.y != cur) {
            if (cur >= 0) flush4(out, cur, c, acc);
            acc = make_float4(0.f, 0.f, 0.f, 0.f);
            cur = m.y;
        }
        float4 a = cvt_h8(h);
        float  v = __int_as_float(m.z);
        acc.x += v * a.x;
        acc.y += v * a.y;
        acc.z += v * a.z;
        acc.w += v * a.w;
    }
    if (cur >= 0) flush4(out, cur, c, acc);
}

// ---------------------------------------------------------------------------
// Launch: memset -> fused(convert+zero+hist) -> scan1 -> reorder -> gatherw
// Inputs: 0 x[1,100000,48] f32 | 1 w[1,48] f32 | 2 rows[1.6M] i32
//         3 cols[1.6M] i32     | 4 vals[1.6M] f32
// Output: f32 [100000, 48]
// ---------------------------------------------------------------------------
extern "C" void kernel_launch(void* const* d_in, const int* in_sizes, int n_in,
                              void* d_out, int out_size) {
    const float* x    = (const float*)d_in[0];
    const float* w    = (const float*)d_in[1];
    const int*   rows = (const int*)  d_in[2];
    const int*   cols = (const int*)  d_in[3];
    const float* vals = (const float*)d_in[4];
    float*       out  = (float*)d_out;

    const int nE = in_sizes[2];
    const int n4 = N_NODES * CHUNKS;               // 1.2M float4 groups

    // 0. zero histogram
    void* count_ptr = nullptr;
    cudaGetSymbolAddress(&count_ptr, g_count);
    cudaMemsetAsync(count_ptr, 0, (N_NODES + 1) * sizeof(int), 0);

    // 1. fused convert (x*w -> fp16) + zero out + histogram
    convert_hist_kernel<<<(n4 + 255) / 256, 256>>>((const float4*)x,
                                                   (const float4*)w,
                                                   rows, (float4*)out,
                                                   n4, nE);
    // 2. block-local scan
    scan1_kernel<<<SCAN_NBLK, SCAN_TPB>>>();
    // 3. reorder
    {
        int nq = (nE + 3) / 4;
        reorder_kernel<<<(nq + 255) / 256, 256>>>(rows, cols, vals, nE);
    }
    // 4. windowed, perfectly balanced gather
    {
        int nWin = (nE + WIN - 1) / WIN;           // 100000 windows
        int blocks = (nWin + 31) / 32;             // 32 groups per block
        gatherw_kernel<<<blocks, GRP_TPB>>>(out, nE);
    }
}

// round 14
// speedup vs baseline: 1.2049x; 1.0233x over previous
#include <cuda_runtime.h>
#include <cuda_fp16.h>
#include <cstdint>

#define F_DIM     48
#define CHUNKS    12             // 48 floats = 12 float4 per node
#define XH_STRIDE 64             // fp16 row padded to 64 halves = 128B
#define N_NODES   100000
#define N_EDGES   1600000
#define WIN       16             // edges per 12-lane group (fixed window)
#define GRP_TPB   384            // 32 groups of 12 lanes per block
#define BLK_EDGES 512            // 32 groups * 16 edges

#define SCAN_TPB   1024
#define SCAN_ELEMS (N_NODES + 1)
#define SCAN_NBLK  ((SCAN_ELEMS + SCAN_TPB - 1) / SCAN_TPB)     // 98

// ---------------------------------------------------------------------------
// Scratch (__device__ globals — no allocation)
// ---------------------------------------------------------------------------
__device__ int    g_count[N_NODES + 1];      // counts -> block-local scan -> cursors
__device__ int    g_blocksums[128];
__device__ int4   g_emeta[N_EDGES];          // row-sorted {col, row, val-bits, 0}
__device__ __half g_xh[N_NODES * XH_STRIDE]; // fp16 x*w, 128B rows (12.8MB)

// ---------------------------------------------------------------------------
// 1. fused: xh = x*w -> fp16 (padded rows), zero out, histogram RED.
// ---------------------------------------------------------------------------
__global__ __launch_bounds__(256)
void convert_hist_kernel(const float4* __restrict__ x4,
                         const float4* __restrict__ w4,
                         const int*    __restrict__ rows,
                         float4*       __restrict__ out4,
                         int n4, int nE) {
    int i = blockIdx.x * blockDim.x + threadIdx.x;
    if (i < n4) {
        int node = i / CHUNKS;
        int c    = i - node * CHUNKS;
        float4 v  = x4[i];
        float4 wv = __ldg(w4 + c);
        v.x *= wv.x; v.y *= wv.y; v.z *= wv.z; v.w *= wv.w;
        __half2 h0 = __floats2half2_rn(v.x, v.y);
        __half2 h1 = __floats2half2_rn(v.z, v.w);
        uint2 packed;
        packed.x = *reinterpret_cast<unsigned int*>(&h0);
        packed.y = *reinterpret_cast<unsigned int*>(&h1);
        *reinterpret_cast<uint2*>(g_xh + (size_t)node * XH_STRIDE + c * 4) = packed;
        out4[i] = make_float4(0.f, 0.f, 0.f, 0.f);   // RED target must be 0
    }
    int e = i * 4;
    if (e + 3 < nE) {
        int4 r = *reinterpret_cast<const int4*>(rows + e);
        atomicAdd(&g_count[r.x + 1], 1);
        atomicAdd(&g_count[r.y + 1], 1);
        atomicAdd(&g_count[r.z + 1], 1);
        atomicAdd(&g_count[r.w + 1], 1);
    } else if (e < nE) {
        for (; e < nE; e++) atomicAdd(&g_count[rows[e] + 1], 1);
    }
}

// ---------------------------------------------------------------------------
// 2. scan1: block-local inclusive scan + block sums (consumer-side fixup)
// ---------------------------------------------------------------------------
__global__ __launch_bounds__(SCAN_TPB)
void scan1_kernel() {
    __shared__ int buf[2][SCAN_TPB];
    int t = threadIdx.x;
    int idx = blockIdx.x * SCAN_TPB + t;
    int v = (idx < SCAN_ELEMS) ? g_count[idx] : 0;
    int src = 0;
    buf[0][t] = v;
    __syncthreads();
    #pragma unroll
    for (int off = 1; off < SCAN_TPB; off <<= 1) {
        int val = buf[src][t];
        if (t >= off) val += buf[src][t - off];
        buf[src ^ 1][t] = val;
        src ^= 1;
        __syncthreads();
    }
    if (idx < SCAN_ELEMS) g_count[idx] = buf[src][t];
    if (t == SCAN_TPB - 1) g_blocksums[blockIdx.x] = buf[src][t];
}

// ---------------------------------------------------------------------------
// Helper: exclusive prefixes of the <=98 block sums, in smem.
// ---------------------------------------------------------------------------
__device__ __forceinline__ void load_block_prefixes(int* s_bpre, int t) {
    __shared__ int tmp[2][128];
    if (t < 128) tmp[0][t] = (t < SCAN_NBLK) ? g_blocksums[t] : 0;
    __syncthreads();
    int src = 0;
    #pragma unroll
    for (int off = 1; off < 128; off <<= 1) {
        if (t < 128) {
            int val = tmp[src][t];
            if (t >= off) val += tmp[src][t - off];
            tmp[src ^ 1][t] = val;
        }
        src ^= 1;
        __syncthreads();
    }
    if (t < 128) s_bpre[t] = (t == 0) ? 0 : tmp[src][t - 1];
    __syncthreads();
}

// ---------------------------------------------------------------------------
// 3. reorder: p = atomicAdd(&g_count[row],1) + bprefix[row>>10].
//    4 edges/thread. Writes {col,row,val,0}.
// ---------------------------------------------------------------------------
__global__ __launch_bounds__(256)
void reorder_kernel(const int*   __restrict__ rows,
                    const int*   __restrict__ cols,
                    const float* __restrict__ vals, int nE) {
    __shared__ int s_bpre[128];
    load_block_prefixes(s_bpre, threadIdx.x);

    int q = blockIdx.x * blockDim.x + threadIdx.x;
    int e = q * 4;
    if (e + 3 < nE) {
        int4   r  = *reinterpret_cast<const int4*>(rows + e);
        int4   cc = *reinterpret_cast<const int4*>(cols + e);
        float4 vv = *reinterpret_cast<const float4*>(vals + e);
        int p0 = atomicAdd(&g_count[r.x], 1) + s_bpre[r.x >> 10];
        int p1 = atomicAdd(&g_count[r.y], 1) + s_bpre[r.y >> 10];
        int p2 = atomicAdd(&g_count[r.z], 1) + s_bpre[r.z >> 10];
        int p3 = atomicAdd(&g_count[r.w], 1) + s_bpre[r.w >> 10];
        g_emeta[p0] = make_int4(cc.x, r.x, __float_as_int(vv.x), 0);
        g_emeta[p1] = make_int4(cc.y, r.y, __float_as_int(vv.y), 0);
        g_emeta[p2] = make_int4(cc.z, r.z, __float_as_int(vv.z), 0);
        g_emeta[p3] = make_int4(cc.w, r.w, __float_as_int(vv.w), 0);
    } else if (e < nE) {
        for (; e < nE; e++) {
            int r = rows[e];
            int p = atomicAdd(&g_count[r], 1) + s_bpre[r >> 10];
            g_emeta[p] = make_int4(cols[e], r, __float_as_int(vals[e]), 0);
        }
    }
}

// ---------------------------------------------------------------------------
// 4. windowed gather with SMEM meta staging.
//    Block stages its 512 edge records (8KB) coalesced into smem, then each
//    12-lane group processes exactly 16 edges. Row-boundary flushes use
//    PREDICATED red.v4 (no divergent branches).
// ---------------------------------------------------------------------------
__device__ __forceinline__ float4 cvt_h8(uint2 raw) {
    __half2 h0 = *reinterpret_cast<__half2*>(&raw.x);
    __half2 h1 = *reinterpret_cast<__half2*>(&raw.y);
    float2 f0 = __half22float2(h0);
    float2 f1 = __half22float2(h1);
    return make_float4(f0.x, f0.y, f1.x, f1.y);
}

// Predicated flush: if (flag) red.global.add.v4.f32 [out + row*F_DIM + c*4]
__device__ __forceinline__ void flush4_pred(float* __restrict__ out,
                                            int row, int c, float4 acc,
                                            int flag) {
    float* dst = out + (size_t)row * F_DIM + c * 4;
    asm volatile("{\n\t"
                 ".reg .pred p;\n\t"
                 "setp.ne.s32 p, %5, 0;\n\t"
                 "@p red.global.add.v4.f32 [%0], {%1, %2, %3, %4};\n\t"
                 "}"
                 :: "l"(dst), "f"(acc.x), "f"(acc.y), "f"(acc.z), "f"(acc.w),
                    "r"(flag)
                 : "memory");
}

__global__ __launch_bounds__(GRP_TPB)
void gatherw_kernel(float* __restrict__ out, int nE) {
    __shared__ int4 s_meta[BLK_EDGES];         // 8KB

    int t = threadIdx.x;
    int base = blockIdx.x * BLK_EDGES;

    // coalesced staging of this block's edge records
    #pragma unroll
    for (int i = t; i < BLK_EDGES; i += GRP_TPB) {
        int e = base + i;
        s_meta[i] = (e < nE) ? __ldg(g_emeta + e) : make_int4(0, -1, 0, 0);
    }
    __syncthreads();

    int grp = t / 12;               // 0..31
    int c   = t - grp * 12;         // 0..11
    int i0  = grp * WIN;

    int    cur = -1;
    float4 acc = make_float4(0.f, 0.f, 0.f, 0.f);

    #pragma unroll
    for (int k = 0; k < WIN; k += 4) {
        int4 m0 = s_meta[i0 + k + 0];
        int4 m1 = s_meta[i0 + k + 1];
        int4 m2 = s_meta[i0 + k + 2];
        int4 m3 = s_meta[i0 + k + 3];
        uint2 h0 = *reinterpret_cast<const uint2*>(g_xh + (size_t)m0.x * XH_STRIDE + c * 4);
        uint2 h1 = *reinterpret_cast<const uint2*>(g_xh + (size_t)m1.x * XH_STRIDE + c * 4);
        uint2 h2 = *reinterpret_cast<const uint2*>(g_xh + (size_t)m2.x * XH_STRIDE + c * 4);
        uint2 h3 = *reinterpret_cast<const uint2*>(g_xh + (size_t)m3.x * XH_STRIDE + c * 4);

        #pragma unroll
        for (int j = 0; j < 4; j++) {
            int4  m = (j == 0) ? m0 : (j == 1) ? m1 : (j == 2) ? m2 : m3;
            uint2 h = (j == 0) ? h0 : (j == 1) ? h1 : (j == 2) ? h2 : h3;
            int nb = (m.y != cur);                     // new row?
            flush4_pred(out, (cur >= 0) ? cur : 0, c, acc, nb && (cur >= 0));
            // reset accumulator on boundary (select, no branch)
            float z = nb ? 0.f : 1.f;
            acc.x *= z; acc.y *= z; acc.z *= z; acc.w *= z;
            cur = m.y;
            float4 a = cvt_h8(h);
            float  v = __int_as_float(m.z);
            acc.x += v * a.x;
            acc.y += v * a.y;
            acc.z += v * a.z;
            acc.w += v * a.w;
        }
    }
    flush4_pred(out, (cur >= 0) ? cur : 0, c, acc, cur >= 0);
}

// ---------------------------------------------------------------------------
// Launch: memset -> fused(convert+zero+hist) -> scan1 -> reorder -> gatherw
// Inputs: 0 x[1,100000,48] f32 | 1 w[1,48] f32 | 2 rows[1.6M] i32
//         3 cols[1.6M] i32     | 4 vals[1.6M] f32
// Output: f32 [100000, 48]
// ---------------------------------------------------------------------------
extern "C" void kernel_launch(void* const* d_in, const int* in_sizes, int n_in,
                              void* d_out, int out_size) {
    const float* x    = (const float*)d_in[0];
    const float* w    = (const float*)d_in[1];
    const int*   rows = (const int*)  d_in[2];
    const int*   cols = (const int*)  d_in[3];
    const float* vals = (const float*)d_in[4];
    float*       out  = (float*)d_out;

    const int nE = in_sizes[2];
    const int n4 = N_NODES * CHUNKS;               // 1.2M float4 groups

    // 0. zero histogram
    void* count_ptr = nullptr;
    cudaGetSymbolAddress(&count_ptr, g_count);
    cudaMemsetAsync(count_ptr, 0, (N_NODES + 1) * sizeof(int), 0);

    // 1. fused convert (x*w -> fp16) + zero out + histogram
    convert_hist_kernel<<<(n4 + 255) / 256, 256>>>((const float4*)x,
                                                   (const float4*)w,
                                                   rows, (float4*)out,
                                                   n4, nE);
    // 2. block-local scan
    scan1_kernel<<<SCAN_NBLK, SCAN_TPB>>>();
    // 3. reorder
    {
        int nq = (nE + 3) / 4;
        reorder_kernel<<<(nq + 255) / 256, 256>>>(rows, cols, vals, nE);
    }
    // 4. windowed gather with smem meta staging
    {
        int blocks = (nE + BLK_EDGES - 1) / BLK_EDGES;   // 3125
        gatherw_kernel<<<blocks, GRP_TPB>>>(out, nE);
    }
}

// round 15
// speedup vs baseline: 1.2872x; 1.0683x over previous
#include <cuda_runtime.h>
#include <cuda_fp16.h>
#include <cstdint>

#define F_DIM     48
#define CHUNKS    12             // 48 floats = 12 float4 per node
#define XH_STRIDE 64             // fp16 row padded to 64 halves = 128B
#define N_NODES   100000
#define N_EDGES   1600000
#define WIN       16             // edges per 12-lane group (fixed window)
#define GRP_TPB   384            // 32 groups of 12 lanes per block
#define BLK_EDGES 512            // 32 groups * 16 edges

#define SCAN_TPB   1024
#define SCAN_ELEMS (N_NODES + 1)
#define SCAN_NBLK  ((SCAN_ELEMS + SCAN_TPB - 1) / SCAN_TPB)     // 98

// Packed edge record: [56:40)=row(17b) [40:16)=col(24b field,17b used) [16:0)=val fp16
__device__ __forceinline__ unsigned long long pack_edge(int row, int col,
                                                        unsigned short vh) {
    return ((unsigned long long)row << 40) |
           ((unsigned long long)(unsigned)col << 16) |
           (unsigned long long)vh;
}

// ---------------------------------------------------------------------------
// Scratch (__device__ globals — no allocation)
// ---------------------------------------------------------------------------
__device__ int                g_count[N_NODES + 1];
__device__ int                g_blocksums[128];
__device__ unsigned long long g_epack[N_EDGES];        // 12.8MB packed records
__device__ __half             g_xh[N_NODES * XH_STRIDE]; // fp16 x*w (12.8MB)

// ---------------------------------------------------------------------------
// 1. fused: xh = x*w -> fp16 (padded rows), zero out, histogram RED.
// ---------------------------------------------------------------------------
__global__ __launch_bounds__(256)
void convert_hist_kernel(const float4* __restrict__ x4,
                         const float4* __restrict__ w4,
                         const int*    __restrict__ rows,
                         float4*       __restrict__ out4,
                         int n4, int nE) {
    int i = blockIdx.x * blockDim.x + threadIdx.x;
    if (i < n4) {
        int node = i / CHUNKS;
        int c    = i - node * CHUNKS;
        float4 v  = x4[i];
        float4 wv = __ldg(w4 + c);
        v.x *= wv.x; v.y *= wv.y; v.z *= wv.z; v.w *= wv.w;
        __half2 h0 = __floats2half2_rn(v.x, v.y);
        __half2 h1 = __floats2half2_rn(v.z, v.w);
        uint2 packed;
        packed.x = *reinterpret_cast<unsigned int*>(&h0);
        packed.y = *reinterpret_cast<unsigned int*>(&h1);
        *reinterpret_cast<uint2*>(g_xh + (size_t)node * XH_STRIDE + c * 4) = packed;
        out4[i] = make_float4(0.f, 0.f, 0.f, 0.f);   // RED target must be 0
    }
    int e = i * 4;
    if (e + 3 < nE) {
        int4 r = *reinterpret_cast<const int4*>(rows + e);
        atomicAdd(&g_count[r.x + 1], 1);
        atomicAdd(&g_count[r.y + 1], 1);
        atomicAdd(&g_count[r.z + 1], 1);
        atomicAdd(&g_count[r.w + 1], 1);
    } else if (e < nE) {
        for (; e < nE; e++) atomicAdd(&g_count[rows[e] + 1], 1);
    }
}

// ---------------------------------------------------------------------------
// 2. scan1: block-local inclusive scan + block sums (consumer-side fixup)
// ---------------------------------------------------------------------------
__global__ __launch_bounds__(SCAN_TPB)
void scan1_kernel() {
    __shared__ int buf[2][SCAN_TPB];
    int t = threadIdx.x;
    int idx = blockIdx.x * SCAN_TPB + t;
    int v = (idx < SCAN_ELEMS) ? g_count[idx] : 0;
    int src = 0;
    buf[0][t] = v;
    __syncthreads();
    #pragma unroll
    for (int off = 1; off < SCAN_TPB; off <<= 1) {
        int val = buf[src][t];
        if (t >= off) val += buf[src][t - off];
        buf[src ^ 1][t] = val;
        src ^= 1;
        __syncthreads();
    }
    if (idx < SCAN_ELEMS) g_count[idx] = buf[src][t];
    if (t == SCAN_TPB - 1) g_blocksums[blockIdx.x] = buf[src][t];
}

// ---------------------------------------------------------------------------
// Helper: exclusive prefixes of the <=98 block sums, in smem.
// ---------------------------------------------------------------------------
__device__ __forceinline__ void load_block_prefixes(int* s_bpre, int t) {
    __shared__ int tmp[2][128];
    if (t < 128) tmp[0][t] = (t < SCAN_NBLK) ? g_blocksums[t] : 0;
    __syncthreads();
    int src = 0;
    #pragma unroll
    for (int off = 1; off < 128; off <<= 1) {
        if (t < 128) {
            int val = tmp[src][t];
            if (t >= off) val += tmp[src][t - off];
            tmp[src ^ 1][t] = val;
        }
        src ^= 1;
        __syncthreads();
    }
    if (t < 128) s_bpre[t] = (t == 0) ? 0 : tmp[src][t - 1];
    __syncthreads();
}

// ---------------------------------------------------------------------------
// 3. reorder: p = atomicAdd(&g_count[row],1) + bprefix[row>>10].
//    4 edges/thread; single 8B packed scatter store per edge.
// ---------------------------------------------------------------------------
__global__ __launch_bounds__(256)
void reorder_kernel(const int*   __restrict__ rows,
                    const int*   __restrict__ cols,
                    const float* __restrict__ vals, int nE) {
    __shared__ int s_bpre[128];
    load_block_prefixes(s_bpre, threadIdx.x);

    int q = blockIdx.x * blockDim.x + threadIdx.x;
    int e = q * 4;
    if (e + 3 < nE) {
        int4   r  = *reinterpret_cast<const int4*>(rows + e);
        int4   cc = *reinterpret_cast<const int4*>(cols + e);
        float4 vv = *reinterpret_cast<const float4*>(vals + e);
        int p0 = atomicAdd(&g_count[r.x], 1) + s_bpre[r.x >> 10];
        int p1 = atomicAdd(&g_count[r.y], 1) + s_bpre[r.y >> 10];
        int p2 = atomicAdd(&g_count[r.z], 1) + s_bpre[r.z >> 10];
        int p3 = atomicAdd(&g_count[r.w], 1) + s_bpre[r.w >> 10];
        g_epack[p0] = pack_edge(r.x, cc.x, __half_as_ushort(__float2half_rn(vv.x)));
        g_epack[p1] = pack_edge(r.y, cc.y, __half_as_ushort(__float2half_rn(vv.y)));
        g_epack[p2] = pack_edge(r.z, cc.z, __half_as_ushort(__float2half_rn(vv.z)));
        g_epack[p3] = pack_edge(r.w, cc.w, __half_as_ushort(__float2half_rn(vv.w)));
    } else if (e < nE) {
        for (; e < nE; e++) {
            int r = rows[e];
            int p = atomicAdd(&g_count[r], 1) + s_bpre[r >> 10];
            g_epack[p] = pack_edge(r, cols[e],
                                   __half_as_ushort(__float2half_rn(vals[e])));
        }
    }
}

// ---------------------------------------------------------------------------
// 4. windowed gather, 8B packed meta staged in smem (4KB/block).
//    12-lane group x 16 edges; predicated red.v4 flush on row boundaries.
// ---------------------------------------------------------------------------
__device__ __forceinline__ float4 cvt_h8(uint2 raw) {
    __half2 h0 = *reinterpret_cast<__half2*>(&raw.x);
    __half2 h1 = *reinterpret_cast<__half2*>(&raw.y);
    float2 f0 = __half22float2(h0);
    float2 f1 = __half22float2(h1);
    return make_float4(f0.x, f0.y, f1.x, f1.y);
}

__device__ __forceinline__ void flush4_pred(float* __restrict__ out,
                                            int row, int c, float4 acc,
                                            int flag) {
    float* dst = out + (size_t)row * F_DIM + c * 4;
    asm volatile("{\n\t"
                 ".reg .pred p;\n\t"
                 "setp.ne.s32 p, %5, 0;\n\t"
                 "@p red.global.add.v4.f32 [%0], {%1, %2, %3, %4};\n\t"
                 "}"
                 :: "l"(dst), "f"(acc.x), "f"(acc.y), "f"(acc.z), "f"(acc.w),
                    "r"(flag)
                 : "memory");
}

__global__ __launch_bounds__(GRP_TPB)
void gatherw_kernel(float* __restrict__ out, int nE) {
    __shared__ unsigned long long s_meta[BLK_EDGES];   // 4KB

    int t = threadIdx.x;
    int base = blockIdx.x * BLK_EDGES;

    // coalesced staging; pad = row sentinel 0x1FFFF (>=N_NODES), val 0
    const unsigned long long PAD = pack_edge(0x1FFFF, 0, 0);
    #pragma unroll
    for (int i = t; i < BLK_EDGES; i += GRP_TPB) {
        int e = base + i;
        s_meta[i] = (e < nE) ? __ldg(g_epack + e) : PAD;
    }
    __syncthreads();

    int grp = t / 12;               // 0..31
    int c   = t - grp * 12;         // 0..11
    int i0  = grp * WIN;

    int    cur = -1;
    float4 acc = make_float4(0.f, 0.f, 0.f, 0.f);

    #pragma unroll
    for (int k = 0; k < WIN; k += 4) {
        unsigned long long m0 = s_meta[i0 + k + 0];
        unsigned long long m1 = s_meta[i0 + k + 1];
        unsigned long long m2 = s_meta[i0 + k + 2];
        unsigned long long m3 = s_meta[i0 + k + 3];
        int col0 = (int)((m0 >> 16) & 0xFFFFFF);
        int col1 = (int)((m1 >> 16) & 0xFFFFFF);
        int col2 = (int)((m2 >> 16) & 0xFFFFFF);
        int col3 = (int)((m3 >> 16) & 0xFFFFFF);
        uint2 h0 = *reinterpret_cast<const uint2*>(g_xh + (size_t)col0 * XH_STRIDE + c * 4);
        uint2 h1 = *reinterpret_cast<const uint2*>(g_xh + (size_t)col1 * XH_STRIDE + c * 4);
        uint2 h2 = *reinterpret_cast<const uint2*>(g_xh + (size_t)col2 * XH_STRIDE + c * 4);
        uint2 h3 = *reinterpret_cast<const uint2*>(g_xh + (size_t)col3 * XH_STRIDE + c * 4);

        #pragma unroll
        for (int j = 0; j < 4; j++) {
            unsigned long long m = (j == 0) ? m0 : (j == 1) ? m1 : (j == 2) ? m2 : m3;
            uint2 h = (j == 0) ? h0 : (j == 1) ? h1 : (j == 2) ? h2 : h3;
            int row = (int)(m >> 40);
            int nb  = (row != cur);
            flush4_pred(out, (cur >= 0) ? cur : 0, c, acc, nb && (cur >= 0));
            float z = nb ? 0.f : 1.f;
            acc.x *= z; acc.y *= z; acc.z *= z; acc.w *= z;
            cur = row;
            float4 a = cvt_h8(h);
            float  v = __half2float(__ushort_as_half((unsigned short)(m & 0xFFFF)));
            acc.x += v * a.x;
            acc.y += v * a.y;
            acc.z += v * a.z;
            acc.w += v * a.w;
        }
    }
    // suppress final flush for sentinel/pad rows
    flush4_pred(out, (cur >= 0 && cur < N_NODES) ? cur : 0, c, acc,
                (cur >= 0) && (cur < N_NODES));
}

// ---------------------------------------------------------------------------
// Launch: memset -> fused(convert+zero+hist) -> scan1 -> reorder -> gatherw
// Inputs: 0 x[1,100000,48] f32 | 1 w[1,48] f32 | 2 rows[1.6M] i32
//         3 cols[1.6M] i32     | 4 vals[1.6M] f32
// Output: f32 [100000, 48]
// ---------------------------------------------------------------------------
extern "C" void kernel_launch(void* const* d_in, const int* in_sizes, int n_in,
                              void* d_out, int out_size) {
    const float* x    = (const float*)d_in[0];
    const float* w    = (const float*)d_in[1];
    const int*   rows = (const int*)  d_in[2];
    const int*   cols = (const int*)  d_in[3];
    const float* vals = (const float*)d_in[4];
    float*       out  = (float*)d_out;

    const int nE = in_sizes[2];
    const int n4 = N_NODES * CHUNKS;               // 1.2M float4 groups

    // 0. zero histogram
    void* count_ptr = nullptr;
    cudaGetSymbolAddress(&count_ptr, g_count);
    cudaMemsetAsync(count_ptr, 0, (N_NODES + 1) * sizeof(int), 0);

    // 1. fused convert (x*w -> fp16) + zero out + histogram
    convert_hist_kernel<<<(n4 + 255) / 256, 256>>>((const float4*)x,
                                                   (const float4*)w,
                                                   rows, (float4*)out,
                                                   n4, nE);
    // 2. block-local scan
    scan1_kernel<<<SCAN_NBLK, SCAN_TPB>>>();
    // 3. reorder (8B packed records)
    {
        int nq = (nE + 3) / 4;
        reorder_kernel<<<(nq + 255) / 256, 256>>>(rows, cols, vals, nE);
    }
    // 4. windowed gather
    {
        int blocks = (nE + BLK_EDGES - 1) / BLK_EDGES;   // 3125
        gatherw_kernel<<<blocks, GRP_TPB>>>(out, nE);
    }
}

// round 16
// speedup vs baseline: 1.3154x; 1.0219x over previous
#include <cuda_runtime.h>
#include <cuda_fp16.h>
#include <cstdint>

#define F_DIM     48
#define CHUNKS    12             // 48 floats = 12 float4 per node
#define XH_STRIDE 64             // fp16 row padded to 64 halves = 128B
#define N_NODES   100000
#define N_EDGES   1600000
#define WIN       16             // edges per 12-lane group (fixed window)
#define GRP_TPB   384            // 32 groups of 12 lanes per block
#define BLK_EDGES 512            // 32 groups * 16 edges

#define SCAN_TPB   1024
#define SCAN_ELEMS (N_NODES + 1)
#define SCAN_NBLK  ((SCAN_ELEMS + SCAN_TPB - 1) / SCAN_TPB)     // 98

#define ROW_SENTINEL 0x1FFFF     // >= N_NODES, marks padding records

// Packed edge record (uint2):
//   w0 = col * 128      (byte offset of the node's fp16 row in g_xh)
//   w1 = (row << 15) | val_fp16_bits   (val >= 0 -> sign bit 0 -> 15 bits)
__device__ __forceinline__ uint2 pack_edge(int row, int col, unsigned short vh) {
    uint2 r;
    r.x = (unsigned)col << 7;                       // col * 128
    r.y = ((unsigned)row << 15) | (unsigned)vh;     // vh < 0x8000 guaranteed
    return r;
}

// ---------------------------------------------------------------------------
// Scratch (__device__ globals — no allocation)
// ---------------------------------------------------------------------------
__device__ int    g_count[N_NODES + 1];
__device__ int    g_blocksums[128];
__device__ uint2  g_epack[N_EDGES];              // 12.8MB packed records
__device__ __half g_xh[N_NODES * XH_STRIDE];     // fp16 x*w (12.8MB)

// ---------------------------------------------------------------------------
// 1. fused: xh = x*w -> fp16 (padded rows), zero out, histogram RED.
// ---------------------------------------------------------------------------
__global__ __launch_bounds__(256)
void convert_hist_kernel(const float4* __restrict__ x4,
                         const float4* __restrict__ w4,
                         const int*    __restrict__ rows,
                         float4*       __restrict__ out4,
                         int n4, int nE) {
    int i = blockIdx.x * blockDim.x + threadIdx.x;
    if (i < n4) {
        int node = i / CHUNKS;
        int c    = i - node * CHUNKS;
        float4 v  = x4[i];
        float4 wv = __ldg(w4 + c);
        v.x *= wv.x; v.y *= wv.y; v.z *= wv.z; v.w *= wv.w;
        __half2 h0 = __floats2half2_rn(v.x, v.y);
        __half2 h1 = __floats2half2_rn(v.z, v.w);
        uint2 packed;
        packed.x = *reinterpret_cast<unsigned int*>(&h0);
        packed.y = *reinterpret_cast<unsigned int*>(&h1);
        *reinterpret_cast<uint2*>(g_xh + (size_t)node * XH_STRIDE + c * 4) = packed;
        out4[i] = make_float4(0.f, 0.f, 0.f, 0.f);   // RED target must be 0
    }
    int e = i * 4;
    if (e + 3 < nE) {
        int4 r = *reinterpret_cast<const int4*>(rows + e);
        atomicAdd(&g_count[r.x + 1], 1);
        atomicAdd(&g_count[r.y + 1], 1);
        atomicAdd(&g_count[r.z + 1], 1);
        atomicAdd(&g_count[r.w + 1], 1);
    } else if (e < nE) {
        for (; e < nE; e++) atomicAdd(&g_count[rows[e] + 1], 1);
    }
}

// ---------------------------------------------------------------------------
// 2. scan1: block-local inclusive scan + block sums (consumer-side fixup)
// ---------------------------------------------------------------------------
__global__ __launch_bounds__(SCAN_TPB)
void scan1_kernel() {
    __shared__ int buf[2][SCAN_TPB];
    int t = threadIdx.x;
    int idx = blockIdx.x * SCAN_TPB + t;
    int v = (idx < SCAN_ELEMS) ? g_count[idx] : 0;
    int src = 0;
    buf[0][t] = v;
    __syncthreads();
    #pragma unroll
    for (int off = 1; off < SCAN_TPB; off <<= 1) {
        int val = buf[src][t];
        if (t >= off) val += buf[src][t - off];
        buf[src ^ 1][t] = val;
        src ^= 1;
        __syncthreads();
    }
    if (idx < SCAN_ELEMS) g_count[idx] = buf[src][t];
    if (t == SCAN_TPB - 1) g_blocksums[blockIdx.x] = buf[src][t];
}

// ---------------------------------------------------------------------------
// Helper: exclusive prefixes of the <=98 block sums, in smem.
// ---------------------------------------------------------------------------
__device__ __forceinline__ void load_block_prefixes(int* s_bpre, int t) {
    __shared__ int tmp[2][128];
    if (t < 128) tmp[0][t] = (t < SCAN_NBLK) ? g_blocksums[t] : 0;
    __syncthreads();
    int src = 0;
    #pragma unroll
    for (int off = 1; off < 128; off <<= 1) {
        if (t < 128) {
            int val = tmp[src][t];
            if (t >= off) val += tmp[src][t - off];
            tmp[src ^ 1][t] = val;
        }
        src ^= 1;
        __syncthreads();
    }
    if (t < 128) s_bpre[t] = (t == 0) ? 0 : tmp[src][t - 1];
    __syncthreads();
}

// ---------------------------------------------------------------------------
// 3. reorder: p = atomicAdd(&g_count[row],1) + bprefix[row>>10].
//    4 edges/thread; single 8B packed scatter store per edge.
// ---------------------------------------------------------------------------
__global__ __launch_bounds__(256)
void reorder_kernel(const int*   __restrict__ rows,
                    const int*   __restrict__ cols,
                    const float* __restrict__ vals, int nE) {
    __shared__ int s_bpre[128];
    load_block_prefixes(s_bpre, threadIdx.x);

    int q = blockIdx.x * blockDim.x + threadIdx.x;
    int e = q * 4;
    if (e + 3 < nE) {
        int4   r  = *reinterpret_cast<const int4*>(rows + e);
        int4   cc = *reinterpret_cast<const int4*>(cols + e);
        float4 vv = *reinterpret_cast<const float4*>(vals + e);
        int p0 = atomicAdd(&g_count[r.x], 1) + s_bpre[r.x >> 10];
        int p1 = atomicAdd(&g_count[r.y], 1) + s_bpre[r.y >> 10];
        int p2 = atomicAdd(&g_count[r.z], 1) + s_bpre[r.z >> 10];
        int p3 = atomicAdd(&g_count[r.w], 1) + s_bpre[r.w >> 10];
        g_epack[p0] = pack_edge(r.x, cc.x, __half_as_ushort(__float2half_rn(vv.x)));
        g_epack[p1] = pack_edge(r.y, cc.y, __half_as_ushort(__float2half_rn(vv.y)));
        g_epack[p2] = pack_edge(r.z, cc.z, __half_as_ushort(__float2half_rn(vv.z)));
        g_epack[p3] = pack_edge(r.w, cc.w, __half_as_ushort(__float2half_rn(vv.w)));
    } else if (e < nE) {
        for (; e < nE; e++) {
            int r = rows[e];
            int p = atomicAdd(&g_count[r], 1) + s_bpre[r >> 10];
            g_epack[p] = pack_edge(r, cols[e],
                                   __half_as_ushort(__float2half_rn(vals[e])));
        }
    }
}

// ---------------------------------------------------------------------------
// 4. windowed gather: uint2 meta (cheap unpack), 12-lane group x 16 edges,
//    predicated red.v4 flush. Addresses use pre-multiplied col*128 offsets.
// ---------------------------------------------------------------------------
__device__ __forceinline__ float4 cvt_h8(uint2 raw) {
    __half2 h0 = *reinterpret_cast<__half2*>(&raw.x);
    __half2 h1 = *reinterpret_cast<__half2*>(&raw.y);
    float2 f0 = __half22float2(h0);
    float2 f1 = __half22float2(h1);
    return make_float4(f0.x, f0.y, f1.x, f1.y);
}

__device__ __forceinline__ void flush4_pred(float* dst, float4 acc, int flag) {
    asm volatile("{\n\t"
                 ".reg .pred p;\n\t"
                 "setp.ne.s32 p, %5, 0;\n\t"
                 "@p red.global.add.v4.f32 [%0], {%1, %2, %3, %4};\n\t"
                 "}"
                 :: "l"(dst), "f"(acc.x), "f"(acc.y), "f"(acc.z), "f"(acc.w),
                    "r"(flag)
                 : "memory");
}

__global__ __launch_bounds__(GRP_TPB)
void gatherw_kernel(float* __restrict__ out, int nE) {
    __shared__ uint2 s_meta[BLK_EDGES];        // 4KB

    int t = threadIdx.x;
    int base = blockIdx.x * BLK_EDGES;

    const uint2 PAD = make_uint2(0u, (unsigned)ROW_SENTINEL << 15);
    for (int i = t; i < BLK_EDGES; i += GRP_TPB) {
        int e = base + i;
        s_meta[i] = (e < nE) ? __ldg(g_epack + e) : PAD;
    }
    __syncthreads();

    int grp = t / 12;               // 0..31
    int c   = t - grp * 12;         // 0..11
    int i0  = grp * WIN;

    // hoisted per-lane bases
    const char*  xbase = reinterpret_cast<const char*>(g_xh) + c * 8;
    float*       obase = out + c * 4;

    // initialize cur from the first edge -> first boundary test is false
    int    cur = (int)(s_meta[i0].y >> 15);
    float4 acc = make_float4(0.f, 0.f, 0.f, 0.f);

    #pragma unroll
    for (int k = 0; k < WIN; k += 4) {
        uint2 m0 = s_meta[i0 + k + 0];
        uint2 m1 = s_meta[i0 + k + 1];
        uint2 m2 = s_meta[i0 + k + 2];
        uint2 m3 = s_meta[i0 + k + 3];
        uint2 h0 = *reinterpret_cast<const uint2*>(xbase + m0.x);
        uint2 h1 = *reinterpret_cast<const uint2*>(xbase + m1.x);
        uint2 h2 = *reinterpret_cast<const uint2*>(xbase + m2.x);
        uint2 h3 = *reinterpret_cast<const uint2*>(xbase + m3.x);

        #pragma unroll
        for (int j = 0; j < 4; j++) {
            uint2 m = (j == 0) ? m0 : (j == 1) ? m1 : (j == 2) ? m2 : m3;
            uint2 h = (j == 0) ? h0 : (j == 1) ? h1 : (j == 2) ? h2 : h3;
            int row = (int)(m.y >> 15);
            int nb  = (row != cur);
            flush4_pred(obase + (size_t)cur * F_DIM, acc, nb);
            float z = nb ? 0.f : 1.f;
            acc.x *= z; acc.y *= z; acc.z *= z; acc.w *= z;
            cur = row;
            float4 a = cvt_h8(h);
            float  v = __half2float(__ushort_as_half(
                           (unsigned short)(m.y & 0x7FFF)));
            acc.x += v * a.x;
            acc.y += v * a.y;
            acc.z += v * a.z;
            acc.w += v * a.w;
        }
    }
    // final flush; suppress for pad sentinel windows
    flush4_pred(obase + (size_t)((cur < N_NODES) ? cur : 0) * F_DIM, acc,
                cur < N_NODES);
}

// ---------------------------------------------------------------------------
// Launch: memset -> fused(convert+zero+hist) -> scan1 -> reorder -> gatherw
// Inputs: 0 x[1,100000,48] f32 | 1 w[1,48] f32 | 2 rows[1.6M] i32
//         3 cols[1.6M] i32     | 4 vals[1.6M] f32
// Output: f32 [100000, 48]
// ---------------------------------------------------------------------------
extern "C" void kernel_launch(void* const* d_in, const int* in_sizes, int n_in,
                              void* d_out, int out_size) {
    const float* x    = (const float*)d_in[0];
    const float* w    = (const float*)d_in[1];
    const int*   rows = (const int*)  d_in[2];
    const int*   cols = (const int*)  d_in[3];
    const float* vals = (const float*)d_in[4];
    float*       out  = (float*)d_out;

    const int nE = in_sizes[2];
    const int n4 = N_NODES * CHUNKS;               // 1.2M float4 groups

    // 0. zero histogram
    void* count_ptr = nullptr;
    cudaGetSymbolAddress(&count_ptr, g_count);
    cudaMemsetAsync(count_ptr, 0, (N_NODES + 1) * sizeof(int), 0);

    // 1. fused convert (x*w -> fp16) + zero out + histogram
    convert_hist_kernel<<<(n4 + 255) / 256, 256>>>((const float4*)x,
                                                   (const float4*)w,
                                                   rows, (float4*)out,
                                                   n4, nE);
    // 2. block-local scan
    scan1_kernel<<<SCAN_NBLK, SCAN_TPB>>>();
    // 3. reorder (8B packed records)
    {
        int nq = (nE + 3) / 4;
        reorder_kernel<<<(nq + 255) / 256, 256>>>(rows, cols, vals, nE);
    }
    // 4. windowed gather
    {
        int blocks = (nE + BLK_EDGES - 1) / BLK_EDGES;   // 3125
        gatherw_kernel<<<blocks, GRP_TPB>>>(out, nE);
    }
}

// round 17
// speedup vs baseline: 1.3213x; 1.0045x over previous
#include <cuda_runtime.h>
#include <cuda_fp16.h>
#include <cstdint>

#define F_DIM     48
#define CHUNKS    12             // 48 floats = 12 float4 per node
#define XH_STRIDE 64             // fp16 row padded to 64 halves = 128B
#define N_NODES   100000
#define N_EDGES   1600000
#define WIN       16             // edges per 12-lane group (fixed window)
#define GRP_TPB   384            // 32 groups of 12 lanes per block
#define BLK_EDGES 512            // 32 groups * 16 edges

#define SCAN_TPB   1024
#define SCAN_ELEMS (N_NODES + 1)
#define SCAN_NBLK  ((SCAN_ELEMS + SCAN_TPB - 1) / SCAN_TPB)     // 98

#define ROW_SENTINEL 0x1FFFF     // >= N_NODES, marks padding records

// Packed edge record (uint2):
//   w0 = col * 128      (byte offset of the node's fp16 row in g_xh)
//   w1 = (row << 15) | val_fp16_bits   (val >= 0 -> sign bit 0 -> 15 bits)
__device__ __forceinline__ uint2 pack_edge(int row, int col, unsigned short vh) {
    uint2 r;
    r.x = (unsigned)col << 7;
    r.y = ((unsigned)row << 15) | (unsigned)vh;
    return r;
}

// ---------------------------------------------------------------------------
// Scratch (__device__ globals — zero-initialized at module load; g_count is
// re-zeroed by gatherw's epilogue every run, so no memset node is needed)
// ---------------------------------------------------------------------------
__device__ int    g_count[N_NODES + 1];
__device__ int    g_blocksums[128];
__device__ uint2  g_epack[N_EDGES];              // 12.8MB packed records
__device__ __half g_xh[N_NODES * XH_STRIDE];     // fp16 x*w (12.8MB)

// ---------------------------------------------------------------------------
// 1. hist: fire-and-forget RED histogram, 4 edges/thread.
//    Requires g_count == 0 on entry (static init / gatherw epilogue).
// ---------------------------------------------------------------------------
__global__ __launch_bounds__(256)
void hist_kernel(const int* __restrict__ rows, int nE) {
    int q = blockIdx.x * blockDim.x + threadIdx.x;
    int e = q * 4;
    if (e + 3 < nE) {
        int4 r = *reinterpret_cast<const int4*>(rows + e);
        atomicAdd(&g_count[r.x + 1], 1);
        atomicAdd(&g_count[r.y + 1], 1);
        atomicAdd(&g_count[r.z + 1], 1);
        atomicAdd(&g_count[r.w + 1], 1);
    } else if (e < nE) {
        for (; e < nE; e++) atomicAdd(&g_count[rows[e] + 1], 1);
    }
}

// ---------------------------------------------------------------------------
// 2. scan1: block-local inclusive scan + block sums (consumer-side fixup)
// ---------------------------------------------------------------------------
__global__ __launch_bounds__(SCAN_TPB)
void scan1_kernel() {
    __shared__ int buf[2][SCAN_TPB];
    int t = threadIdx.x;
    int idx = blockIdx.x * SCAN_TPB + t;
    int v = (idx < SCAN_ELEMS) ? g_count[idx] : 0;
    int src = 0;
    buf[0][t] = v;
    __syncthreads();
    #pragma unroll
    for (int off = 1; off < SCAN_TPB; off <<= 1) {
        int val = buf[src][t];
        if (t >= off) val += buf[src][t - off];
        buf[src ^ 1][t] = val;
        src ^= 1;
        __syncthreads();
    }
    if (idx < SCAN_ELEMS) g_count[idx] = buf[src][t];
    if (t == SCAN_TPB - 1) g_blocksums[blockIdx.x] = buf[src][t];
}

// ---------------------------------------------------------------------------
// Helper: exclusive prefixes of the <=98 block sums, in smem.
// ---------------------------------------------------------------------------
__device__ __forceinline__ void load_block_prefixes(int* s_bpre, int t) {
    __shared__ int tmp[2][128];
    if (t < 128) tmp[0][t] = (t < SCAN_NBLK) ? g_blocksums[t] : 0;
    __syncthreads();
    int src = 0;
    #pragma unroll
    for (int off = 1; off < 128; off <<= 1) {
        if (t < 128) {
            int val = tmp[src][t];
            if (t >= off) val += tmp[src][t - off];
            tmp[src ^ 1][t] = val;
        }
        src ^= 1;
        __syncthreads();
    }
    if (t < 128) s_bpre[t] = (t == 0) ? 0 : tmp[src][t - 1];
    __syncthreads();
}

// ---------------------------------------------------------------------------
// 3. reorder + convert + zero-out (fused):
//    a) reorder: p = atomicAdd(&g_count[row],1) + bprefix[row>>10]; 8B store.
//    b) convert: xh = x*w -> fp16 (grid-stride; hides in atomic latency slack)
//       and zero d_out (RED target).
// ---------------------------------------------------------------------------
__global__ __launch_bounds__(256)
void reorder_convert_kernel(const int*    __restrict__ rows,
                            const int*    __restrict__ cols,
                            const float*  __restrict__ vals,
                            const float4* __restrict__ x4,
                            const float4* __restrict__ w4,
                            float4*       __restrict__ out4,
                            int nE, int n4) {
    __shared__ int s_bpre[128];
    load_block_prefixes(s_bpre, threadIdx.x);

    int q = blockIdx.x * blockDim.x + threadIdx.x;
    int nThreads = gridDim.x * blockDim.x;

    // ---- convert + zero-out (streaming, independent of reorder) ----
    for (int i = q; i < n4; i += nThreads) {
        int node = i / CHUNKS;
        int c    = i - node * CHUNKS;
        float4 v  = x4[i];
        float4 wv = __ldg(w4 + c);
        v.x *= wv.x; v.y *= wv.y; v.z *= wv.z; v.w *= wv.w;
        __half2 h0 = __floats2half2_rn(v.x, v.y);
        __half2 h1 = __floats2half2_rn(v.z, v.w);
        uint2 packed;
        packed.x = *reinterpret_cast<unsigned int*>(&h0);
        packed.y = *reinterpret_cast<unsigned int*>(&h1);
        *reinterpret_cast<uint2*>(g_xh + (size_t)node * XH_STRIDE + c * 4) = packed;
        out4[i] = make_float4(0.f, 0.f, 0.f, 0.f);
    }

    // ---- reorder: 4 edges/thread ----
    int e = q * 4;
    if (e + 3 < nE) {
        int4   r  = *reinterpret_cast<const int4*>(rows + e);
        int4   cc = *reinterpret_cast<const int4*>(cols + e);
        float4 vv = *reinterpret_cast<const float4*>(vals + e);
        int p0 = atomicAdd(&g_count[r.x], 1) + s_bpre[r.x >> 10];
        int p1 = atomicAdd(&g_count[r.y], 1) + s_bpre[r.y >> 10];
        int p2 = atomicAdd(&g_count[r.z], 1) + s_bpre[r.z >> 10];
        int p3 = atomicAdd(&g_count[r.w], 1) + s_bpre[r.w >> 10];
        g_epack[p0] = pack_edge(r.x, cc.x, __half_as_ushort(__float2half_rn(vv.x)));
        g_epack[p1] = pack_edge(r.y, cc.y, __half_as_ushort(__float2half_rn(vv.y)));
        g_epack[p2] = pack_edge(r.z, cc.z, __half_as_ushort(__float2half_rn(vv.z)));
        g_epack[p3] = pack_edge(r.w, cc.w, __half_as_ushort(__float2half_rn(vv.w)));
    } else if (e < nE) {
        for (; e < nE; e++) {
            int r = rows[e];
            int p = atomicAdd(&g_count[r], 1) + s_bpre[r >> 10];
            g_epack[p] = pack_edge(r, cols[e],
                                   __half_as_ushort(__float2half_rn(vals[e])));
        }
    }
}

// ---------------------------------------------------------------------------
// 4. windowed gather: uint2 meta staged in smem, 12-lane group x 16 edges,
//    predicated red.v4 flush. Epilogue re-zeroes g_count for the next run.
// ---------------------------------------------------------------------------
__device__ __forceinline__ float4 cvt_h8(uint2 raw) {
    __half2 h0 = *reinterpret_cast<__half2*>(&raw.x);
    __half2 h1 = *reinterpret_cast<__half2*>(&raw.y);
    float2 f0 = __half22float2(h0);
    float2 f1 = __half22float2(h1);
    return make_float4(f0.x, f0.y, f1.x, f1.y);
}

__device__ __forceinline__ void flush4_pred(float* dst, float4 acc, int flag) {
    asm volatile("{\n\t"
                 ".reg .pred p;\n\t"
                 "setp.ne.s32 p, %5, 0;\n\t"
                 "@p red.global.add.v4.f32 [%0], {%1, %2, %3, %4};\n\t"
                 "}"
                 :: "l"(dst), "f"(acc.x), "f"(acc.y), "f"(acc.z), "f"(acc.w),
                    "r"(flag)
                 : "memory");
}

__global__ __launch_bounds__(GRP_TPB)
void gatherw_kernel(float* __restrict__ out, int nE) {
    __shared__ uint2 s_meta[BLK_EDGES];        // 4KB

    int t = threadIdx.x;
    int base = blockIdx.x * BLK_EDGES;

    const uint2 PAD = make_uint2(0u, (unsigned)ROW_SENTINEL << 15);
    for (int i = t; i < BLK_EDGES; i += GRP_TPB) {
        int e = base + i;
        s_meta[i] = (e < nE) ? __ldg(g_epack + e) : PAD;
    }
    __syncthreads();

    int grp = t / 12;               // 0..31
    int c   = t - grp * 12;         // 0..11
    int i0  = grp * WIN;

    const char* xbase = reinterpret_cast<const char*>(g_xh) + c * 8;
    float*      obase = out + c * 4;

    int    cur = (int)(s_meta[i0].y >> 15);
    float4 acc = make_float4(0.f, 0.f, 0.f, 0.f);

    #pragma unroll
    for (int k = 0; k < WIN; k += 4) {
        uint2 m0 = s_meta[i0 + k + 0];
        uint2 m1 = s_meta[i0 + k + 1];
        uint2 m2 = s_meta[i0 + k + 2];
        uint2 m3 = s_meta[i0 + k + 3];
        uint2 h0 = *reinterpret_cast<const uint2*>(xbase + m0.x);
        uint2 h1 = *reinterpret_cast<const uint2*>(xbase + m1.x);
        uint2 h2 = *reinterpret_cast<const uint2*>(xbase + m2.x);
        uint2 h3 = *reinterpret_cast<const uint2*>(xbase + m3.x);

        #pragma unroll
        for (int j = 0; j < 4; j++) {
            uint2 m = (j == 0) ? m0 : (j == 1) ? m1 : (j == 2) ? m2 : m3;
            uint2 h = (j == 0) ? h0 : (j == 1) ? h1 : (j == 2) ? h2 : h3;
            int row = (int)(m.y >> 15);
            int nb  = (row != cur);
            flush4_pred(obase + (size_t)cur * F_DIM, acc, nb);
            float z = nb ? 0.f : 1.f;
            acc.x *= z; acc.y *= z; acc.z *= z; acc.w *= z;
            cur = row;
            float4 a = cvt_h8(h);
            float  v = __half2float(__ushort_as_half(
                           (unsigned short)(m.y & 0x7FFF)));
            acc.x += v * a.x;
            acc.y += v * a.y;
            acc.z += v * a.z;
            acc.w += v * a.w;
        }
    }
    flush4_pred(obase + (size_t)((cur < N_NODES) ? cur : 0) * F_DIM, acc,
                cur < N_NODES);

    // Epilogue: re-zero g_count for the next invocation (replaces the
    // memset graph node). gatherw itself never reads g_count.
    int idx = blockIdx.x * GRP_TPB + t;     // 1.2M threads >= 100001
    if (idx < SCAN_ELEMS) g_count[idx] = 0;
}

// ---------------------------------------------------------------------------
// Launch: hist -> scan1 -> reorder+convert -> gatherw   (4 nodes)
// Inputs: 0 x[1,100000,48] f32 | 1 w[1,48] f32 | 2 rows[1.6M] i32
//         3 cols[1.6M] i32     | 4 vals[1.6M] f32
// Output: f32 [100000, 48]
// ---------------------------------------------------------------------------
extern "C" void kernel_launch(void* const* d_in, const int* in_sizes, int n_in,
                              void* d_out, int out_size) {
    const float* x    = (const float*)d_in[0];
    const float* w    = (const float*)d_in[1];
    const int*   rows = (const int*)  d_in[2];
    const int*   cols = (const int*)  d_in[3];
    const float* vals = (const float*)d_in[4];
    float*       out  = (float*)d_out;

    const int nE = in_sizes[2];
    const int n4 = N_NODES * CHUNKS;               // 1.2M float4 groups

    // 1. histogram (g_count zeroed by previous gatherw / static init)
    {
        int nq = (nE + 3) / 4;
        hist_kernel<<<(nq + 255) / 256, 256>>>(rows, nE);
    }
    // 2. block-local scan
    scan1_kernel<<<SCAN_NBLK, SCAN_TPB>>>();
    // 3. reorder + convert + zero-out (fused)
    {
        int nq = (nE + 3) / 4;                     // 400k threads
        reorder_convert_kernel<<<(nq + 255) / 256, 256>>>(
            rows, cols, vals, (const float4*)x, (const float4*)w,
            (float4*)out, nE, n4);
    }
    // 4. windowed gather (+ g_count re-zero epilogue)
    {
        int blocks = (nE + BLK_EDGES - 1) / BLK_EDGES;   // 3125
        gatherw_kernel<<<blocks, GRP_TPB>>>(out, nE);
    }
}